// round 7
// baseline (speedup 1.0000x reference)
#include <cuda_runtime.h>

#define QF 64
#define PTS_PER_WARP 288   // multiple of 8; 6945 warps -> 869 blocks <= 888 (6/SM) = ONE wave

__global__ void perslay_zero_kernel(float4* __restrict__ out, int n4) {
    int i = blockIdx.x * blockDim.x + threadIdx.x;
    if (i < n4) out[i] = make_float4(0.f, 0.f, 0.f, 0.f);
}

__device__ __forceinline__ float ex2_approx(float x) {
    float r;
    asm("ex2.approx.f32 %0, %1;" : "=f"(r) : "f"(x));
    return r;
}

// phi(x,y) for one q via pure-FFMA quadratic chain:
//   t = ((A*x + B)*x + C) + (Ay*y + By)*y   == -(ax(x-px))^2-(ay(y-py))^2 in log2 units
//   4 FFMA -> 1 MUFU -> 1 FADD(acc)
__device__ __forceinline__ float gq(float x, float y,
                                    float A, float B, float C,
                                    float Ay, float By)
{
    const float u = fmaf(x, A, B);
    const float v = fmaf(x, u, C);
    const float w = fmaf(y, Ay, By);
    const float t = fmaf(y, w, v);
    return ex2_approx(t);
}

__global__ __launch_bounds__(256, 6) void perslay_kernel(
    const float2* __restrict__ xy,
    const int*    __restrict__ seg,
    const float*  __restrict__ sp,
    const float*  __restrict__ isg,
    float*        __restrict__ out,
    int n)
{
    const int warp_id = blockIdx.x * (blockDim.x >> 5) + (threadIdx.x >> 5);
    const int lane    = threadIdx.x & 31;
    const int start   = warp_id * PTS_PER_WARP;
    if (start >= n) return;
    const int end = min(start + PTS_PER_WARP, n);

    const int q0 = 2 * lane;
    const int q1 = q0 + 1;

    // sqrt(log2 e) folded into sigma scale so a bare ex2 replaces exp.
    const float SL  = 1.2011224087864498f;
    const float px0 = sp[q0],      px1 = sp[q1];
    const float py0 = sp[QF + q0], py1 = sp[QF + q1];
    const float ax0 = isg[q0]      * SL, ax1 = isg[q1]      * SL;
    const float ay0 = isg[QF + q0] * SL, ay1 = isg[QF + q1] * SL;

    const float A0  = -ax0 * ax0,       A1  = -ax1 * ax1;
    const float Ay0 = -ay0 * ay0,       Ay1 = -ay1 * ay1;
    const float B0  = -2.f * A0  * px0, B1  = -2.f * A1  * px1;
    const float By0 = -2.f * Ay0 * py0, By1 = -2.f * Ay1 * py1;
    const float C0  = A0 * px0 * px0 + Ay0 * py0 * py0;
    const float C1  = A1 * px1 * px1 + Ay1 * py1 * py1;

    const float4* __restrict__ cp   = (const float4*)(xy + start);  // 2 pts / float4
    const int*    __restrict__ segp = seg + start;
    float*        __restrict__ outP = out + q0;

    float acc0 = 0.f, acc1 = 0.f;
    int cur = segp[0];

    #define FLUSH() do {                                                   \
        atomicAdd(&outP[cur * QF],     acc0);                              \
        atomicAdd(&outP[cur * QF + 1], acc1);                              \
        acc0 = 0.f; acc1 = 0.f;                                            \
    } while (0)

    #define POINT(X, Y) do {                                               \
        acc0 += gq((X), (Y), A0, B0, C0, Ay0, By0);                        \
        acc1 += gq((X), (Y), A1, B1, C1, Ay1, By1);                        \
    } while (0)

    int p = start;
    // Sorted index invariant: seg[i] >= cur for all i >= p. So
    // seg[p+7] == cur  <=>  the whole 8-chunk belongs to segment 'cur'.
    // One scalar load per chunk, software-pipelined one chunk ahead.
    int slast = (p + 8 <= end) ? segp[7] : 0;
    while (p + 8 <= end) {
        const int my_slast = slast;
        if (p + 16 <= end) slast = segp[15];   // prefetch next chunk's check
        const float4 c01 = cp[0];
        const float4 c23 = cp[1];
        const float4 c45 = cp[2];
        const float4 c67 = cp[3];
        if (my_slast == cur) {
            POINT(c01.x, c01.y);  POINT(c01.z, c01.w);
            POINT(c23.x, c23.y);  POINT(c23.z, c23.w);
            POINT(c45.x, c45.y);  POINT(c45.z, c45.w);
            POINT(c67.x, c67.y);  POINT(c67.z, c67.w);
        } else {
            // Cold arm (~1.6% of chunks): per-point segment tracking.
            int sv;
            sv = segp[0]; if (sv != cur) { FLUSH(); cur = sv; }
            POINT(c01.x, c01.y);
            sv = segp[1]; if (sv != cur) { FLUSH(); cur = sv; }
            POINT(c01.z, c01.w);
            sv = segp[2]; if (sv != cur) { FLUSH(); cur = sv; }
            POINT(c23.x, c23.y);
            sv = segp[3]; if (sv != cur) { FLUSH(); cur = sv; }
            POINT(c23.z, c23.w);
            sv = segp[4]; if (sv != cur) { FLUSH(); cur = sv; }
            POINT(c45.x, c45.y);
            sv = segp[5]; if (sv != cur) { FLUSH(); cur = sv; }
            POINT(c45.z, c45.w);
            sv = segp[6]; if (sv != cur) { FLUSH(); cur = sv; }
            POINT(c67.x, c67.y);
            sv = segp[7]; if (sv != cur) { FLUSH(); cur = sv; }
            POINT(c67.z, c67.w);
        }
        p += 8;
        cp += 4;
        segp += 8;
    }
    for (; p < end; ++p, ++segp) {   // tail (< 8 points)
        const float2 c  = xy[p];
        const int    sv = segp[0];
        if (sv != cur) { FLUSH(); cur = sv; }
        POINT(c.x, c.y);
    }
    FLUSH();

    #undef FLUSH
    #undef POINT
}

extern "C" void kernel_launch(void* const* d_in, const int* in_sizes, int n_in,
                              void* d_out, int out_size) {
    const float2* xy  = (const float2*)d_in[0];
    const int*    seg = (const int*)   d_in[1];
    const float*  sp  = (const float*) d_in[2];
    const float*  isg = (const float*) d_in[3];
    float*        out = (float*)d_out;

    const int n = in_sizes[0] / 2;   // input is [N,2] float32

    const int n4 = out_size >> 2;    // 4096*64 / 4
    perslay_zero_kernel<<<(n4 + 255) / 256, 256>>>((float4*)out, n4);

    const int num_warps = (n + PTS_PER_WARP - 1) / PTS_PER_WARP;
    const int blocks    = (num_warps + 7) / 8;   // 8 warps / block
    perslay_kernel<<<blocks, 256>>>(xy, seg, sp, isg, out, n);
}

// round 8
// speedup vs baseline: 1.1550x; 1.1550x over previous
#include <cuda_runtime.h>

#define QF 64
#define PTS_PER_WARP 432   // multiple of 16; 4630 warps -> 579 blocks <= 592 (4/SM) = ONE wave

__global__ void perslay_zero_kernel(float4* __restrict__ out, int n4) {
    int i = blockIdx.x * blockDim.x + threadIdx.x;
    if (i < n4) out[i] = make_float4(0.f, 0.f, 0.f, 0.f);
}

__device__ __forceinline__ float ex2_approx(float x) {
    float r;
    asm("ex2.approx.f32 %0, %1;" : "=f"(r) : "f"(x));
    return r;
}

// phi(x,y) for one q via pure-FFMA quadratic chain:
//   t = ((A*x + B)*x + C) + (Ay*y + By)*y  == -(ax(x-px))^2-(ay(y-py))^2, log2 units
//   4 FFMA -> 1 MUFU -> 1 FADD(acc)
__device__ __forceinline__ float gq(float x, float y,
                                    float A, float B, float C,
                                    float Ay, float By)
{
    const float u = fmaf(x, A, B);
    const float v = fmaf(x, u, C);
    const float w = fmaf(y, Ay, By);
    const float t = fmaf(y, w, v);
    return ex2_approx(t);
}

__global__ __launch_bounds__(256, 4) void perslay_kernel(
    const float2* __restrict__ xy,
    const int*    __restrict__ seg,
    const float*  __restrict__ sp,
    const float*  __restrict__ isg,
    float*        __restrict__ out,
    int n)
{
    const int warp_id = blockIdx.x * (blockDim.x >> 5) + (threadIdx.x >> 5);
    const int lane    = threadIdx.x & 31;
    const int start   = warp_id * PTS_PER_WARP;
    if (start >= n) return;
    const int end = min(start + PTS_PER_WARP, n);

    const int q0 = 2 * lane;
    const int q1 = q0 + 1;

    // sqrt(log2 e) folded into sigma scale so a bare ex2 replaces exp.
    const float SL  = 1.2011224087864498f;
    const float px0 = sp[q0],      px1 = sp[q1];
    const float py0 = sp[QF + q0], py1 = sp[QF + q1];
    const float ax0 = isg[q0]      * SL, ax1 = isg[q1]      * SL;
    const float ay0 = isg[QF + q0] * SL, ay1 = isg[QF + q1] * SL;

    const float A0  = -ax0 * ax0,       A1  = -ax1 * ax1;
    const float Ay0 = -ay0 * ay0,       Ay1 = -ay1 * ay1;
    const float B0  = -2.f * A0  * px0, B1  = -2.f * A1  * px1;
    const float By0 = -2.f * Ay0 * py0, By1 = -2.f * Ay1 * py1;
    const float C0  = A0 * px0 * px0 + Ay0 * py0 * py0;
    const float C1  = A1 * px1 * px1 + Ay1 * py1 * py1;

    const float4* __restrict__ cp   = (const float4*)(xy + start);  // 2 pts / float4
    const int*    __restrict__ segp = seg + start;
    float*        __restrict__ outP = out + q0;

    // Two accumulators per q break the serial FADD-acc chain.
    float a0a = 0.f, a0b = 0.f, a1a = 0.f, a1b = 0.f;
    int cur = segp[0];

    #define FLUSH() do {                                                   \
        atomicAdd(&outP[cur * QF],     a0a + a0b);                         \
        atomicAdd(&outP[cur * QF + 1], a1a + a1b);                         \
        a0a = 0.f; a0b = 0.f; a1a = 0.f; a1b = 0.f;                        \
    } while (0)

    #define POINT_A(X, Y) do {                                             \
        a0a += gq((X), (Y), A0, B0, C0, Ay0, By0);                         \
        a1a += gq((X), (Y), A1, B1, C1, Ay1, By1);                         \
    } while (0)
    #define POINT_B(X, Y) do {                                             \
        a0b += gq((X), (Y), A0, B0, C0, Ay0, By0);                         \
        a1b += gq((X), (Y), A1, B1, C1, Ay1, By1);                         \
    } while (0)

    int p = start;
    // 16-point chunks: front-batch 8 coord LDG.128 + 1 scalar seg LDG (MLP=9)
    // so a single scoreboard wait is amortized over ~192 math instructions.
    // Sorted invariant: seg[i] >= cur for i >= p, so seg[p+15]==cur <=> the
    // whole 16-chunk belongs to 'cur'.
    for (; p + 16 <= end; p += 16, cp += 8, segp += 16) {
        const float4 cA = cp[0];
        const float4 cB = cp[1];
        const float4 cC = cp[2];
        const float4 cD = cp[3];
        const float4 cE = cp[4];
        const float4 cF = cp[5];
        const float4 cG = cp[6];
        const float4 cH = cp[7];
        const int slast = segp[15];
        if (slast == cur) {
            POINT_A(cA.x, cA.y);  POINT_B(cA.z, cA.w);
            POINT_A(cB.x, cB.y);  POINT_B(cB.z, cB.w);
            POINT_A(cC.x, cC.y);  POINT_B(cC.z, cC.w);
            POINT_A(cD.x, cD.y);  POINT_B(cD.z, cD.w);
            POINT_A(cE.x, cE.y);  POINT_B(cE.z, cE.w);
            POINT_A(cF.x, cF.y);  POINT_B(cF.z, cF.w);
            POINT_A(cG.x, cG.y);  POINT_B(cG.z, cG.w);
            POINT_A(cH.x, cH.y);  POINT_B(cH.z, cH.w);
        } else {
            // Cold arm (~3% of chunks): per-point segment tracking.
            int sv;
            sv = segp[0];  if (sv != cur) { FLUSH(); cur = sv; }
            POINT_A(cA.x, cA.y);
            sv = segp[1];  if (sv != cur) { FLUSH(); cur = sv; }
            POINT_B(cA.z, cA.w);
            sv = segp[2];  if (sv != cur) { FLUSH(); cur = sv; }
            POINT_A(cB.x, cB.y);
            sv = segp[3];  if (sv != cur) { FLUSH(); cur = sv; }
            POINT_B(cB.z, cB.w);
            sv = segp[4];  if (sv != cur) { FLUSH(); cur = sv; }
            POINT_A(cC.x, cC.y);
            sv = segp[5];  if (sv != cur) { FLUSH(); cur = sv; }
            POINT_B(cC.z, cC.w);
            sv = segp[6];  if (sv != cur) { FLUSH(); cur = sv; }
            POINT_A(cD.x, cD.y);
            sv = segp[7];  if (sv != cur) { FLUSH(); cur = sv; }
            POINT_B(cD.z, cD.w);
            sv = segp[8];  if (sv != cur) { FLUSH(); cur = sv; }
            POINT_A(cE.x, cE.y);
            sv = segp[9];  if (sv != cur) { FLUSH(); cur = sv; }
            POINT_B(cE.z, cE.w);
            sv = segp[10]; if (sv != cur) { FLUSH(); cur = sv; }
            POINT_A(cF.x, cF.y);
            sv = segp[11]; if (sv != cur) { FLUSH(); cur = sv; }
            POINT_B(cF.z, cF.w);
            sv = segp[12]; if (sv != cur) { FLUSH(); cur = sv; }
            POINT_A(cG.x, cG.y);
            sv = segp[13]; if (sv != cur) { FLUSH(); cur = sv; }
            POINT_B(cG.z, cG.w);
            sv = segp[14]; if (sv != cur) { FLUSH(); cur = sv; }
            POINT_A(cH.x, cH.y);
            sv = segp[15]; if (sv != cur) { FLUSH(); cur = sv; }
            POINT_B(cH.z, cH.w);
        }
    }
    for (; p < end; ++p, ++segp) {   // tail (< 16 points)
        const float2 c  = xy[p];
        const int    sv = segp[0];
        if (sv != cur) { FLUSH(); cur = sv; }
        POINT_A(c.x, c.y);
    }
    FLUSH();

    #undef FLUSH
    #undef POINT_A
    #undef POINT_B
}

extern "C" void kernel_launch(void* const* d_in, const int* in_sizes, int n_in,
                              void* d_out, int out_size) {
    const float2* xy  = (const float2*)d_in[0];
    const int*    seg = (const int*)   d_in[1];
    const float*  sp  = (const float*) d_in[2];
    const float*  isg = (const float*) d_in[3];
    float*        out = (float*)d_out;

    const int n = in_sizes[0] / 2;   // input is [N,2] float32

    const int n4 = out_size >> 2;    // 4096*64 / 4
    perslay_zero_kernel<<<(n4 + 255) / 256, 256>>>((float4*)out, n4);

    const int num_warps = (n + PTS_PER_WARP - 1) / PTS_PER_WARP;
    const int blocks    = (num_warps + 7) / 8;   // 8 warps / block
    perslay_kernel<<<blocks, 256>>>(xy, seg, sp, isg, out, n);
}